// round 5
// baseline (speedup 1.0000x reference)
#include <cuda_runtime.h>
#include <math.h>

#define NN      2304                    // 48*48
#define BB      2
#define CF      32
#define PCH     3
#define TILE    64
#define NT      (NN / TILE)             // 36
#define TPAIRS  (NT * (NT + 1) / 2)     // 666
#define NWORK   (BB * TPAIRS)           // 1332 tile-pairs
#define NLAUNCH 888                     // 148 SMs x 6 resident, single wave
#define NDOUBLE (NWORK - NLAUNCH)       // 444 blocks do 2 tile-pairs
#define KP      2.8853900817779268f     // 4 / ln(4)
#define CEXP    -5.770780163555851f     // -4 * log2(e)
#define SQ2     1.4142135623730951f

// ---- scratch (no allocations allowed) ----
__device__ float4 g_st4[BB * NN];       // (mu, var, 0.25/var, -)
__device__ float4 g_pa4[BB * NN];       // (sqrt2*pE1..3, q1^2)
__device__ float2 g_pb2[BB * NN];       // (q2^2, q3^2)
__device__ float  g_inorm[BB * NN];     // rsqrt(||f||^2)
__device__ float  g_partial[NLAUNCH];
__device__ int    g_count = 0;

typedef unsigned long long u64;

// ---- packed f32x2 helpers (sm_103a) ----
#define FMA2(d, a, b, c) asm("fma.rn.f32x2 %0, %1, %2, %3;" \
    : "=l"(d) : "l"(a), "l"(b), "l"(c))
#define MUL2(d, a, b) asm("mul.rn.f32x2 %0, %1, %2;" \
    : "=l"(d) : "l"(a), "l"(b))
#define ADD2(d, a, b) asm("add.rn.f32x2 %0, %1, %2;" \
    : "=l"(d) : "l"(a), "l"(b))
#define PACK2(d, x) asm("mov.b64 %0, {%1, %1};" : "=l"(d) : "f"(x))
#define UNPACK2(lo, hi, v) asm("mov.b64 {%0, %1}, %2;" \
    : "=f"(lo), "=f"(hi) : "l"(v))

__device__ __forceinline__ float ex2f(float x) {
    float r; asm("ex2.approx.f32 %0, %1;" : "=f"(r) : "f"(x)); return r;
}
__device__ __forceinline__ float rcpf(float x) {
    float r; asm("rcp.approx.f32 %0, %1;" : "=f"(r) : "f"(x)); return r;
}

// ============================================================
// Kernel A: per-node stats + softmax-derived quantities
// ============================================================
__global__ void precompute_kernel(const float* __restrict__ f,
                                  const float* __restrict__ p) {
    int idx = blockIdx.x * 64 + threadIdx.x;
    if (idx >= BB * NN) return;
    int b = idx / NN;
    int n = idx - b * NN;

    const float* fb = f + (size_t)b * CF * NN + n;
    float s = 0.0f, ss = 0.0f;
#pragma unroll
    for (int c = 0; c < CF; c++) {
        float v = fb[c * NN];
        s += v;
        ss = fmaf(v, v, ss);
    }
    float mu  = s * (1.0f / CF);
    float var = (ss - s * mu) * (1.0f / (CF - 1));
    g_st4[idx]   = make_float4(mu, var, 0.25f / var, 0.0f);
    g_inorm[idx] = rsqrtf(ss);

    const float* pp = p + (size_t)b * 4 * NN + n;
    float e0 = __expf(pp[0]);
    float e1 = __expf(pp[NN]);
    float e2 = __expf(pp[2 * NN]);
    float e3 = __expf(pp[3 * NN]);
    float inv = __fdividef(1.0f, e0 + e1 + e2 + e3);
    float q1 = e1 * inv, q2 = e2 * inv, q3 = e3 * inv;
    float E1 = fmaf(KP * q1, __logf(q1), 1.0f);
    float E2 = fmaf(KP * q2, __logf(q2), 1.0f);
    float E3 = fmaf(KP * q3, __logf(q3), 1.0f);
    g_pa4[idx] = make_float4(SQ2 * q1 * E1, SQ2 * q2 * E2, SQ2 * q3 * E3, q1 * q1);
    g_pb2[idx] = make_float2(q2 * q2, q3 * q3);
}

// ============================================================
// Kernel B: 888 blocks x 128 thr, 1-2 tile-pairs each,
//           4i x 8j micro-tile, f32x2 gram + f32x2 epilogue
// ============================================================
__global__ void __launch_bounds__(128, 6) pair_kernel(const float* __restrict__ f,
                                                      float* __restrict__ out) {
    __shared__ __align__(16) float fi_d[CF][2 * TILE];  // i values duplicated
    __shared__ __align__(16) float fj_s[CF][TILE];
    __shared__ __align__(16) float id_d[9][2 * TILE];   // i stats, duplicated
    __shared__ __align__(16) float js_s[9][TILE];       // j stats (0 = -mu)
    __shared__ float red_s[4];
    __shared__ int   is_last;

    int bid  = blockIdx.x;
    int t    = threadIdx.x;
    int lane = t & 31, warp = t >> 5;
    int tx = t & 7,  ty = t >> 3;      // 8 x 16 threads
    int jx = tx * 8, iy = ty * 4;

    // packed constants
    u64 C13, CM23, CHALF, CEXP2;
    PACK2(C13,   (1.0f / 3.0f));
    PACK2(CM23, (-2.0f / 3.0f));
    PACK2(CHALF, 0.5f);
    PACK2(CEXP2, CEXP);

    float part = 0.0f;
    int nrep = (bid < NDOUBLE) ? 2 : 1;

    for (int rep = 0; rep < nrep; rep++) {
        int tp = bid + rep * NLAUNCH;          // tile-pair index in [0, 1332)
        int b  = tp / TPAIRS;
        int r  = tp - b * TPAIRS;
        int ti = 0;
        while (r >= NT - ti) { r -= NT - ti; ti++; }
        int tj = ti + r;
        int i0 = ti * TILE, j0 = tj * TILE;
        const float* fb = f + (size_t)b * CF * NN;

        if (rep) __syncthreads();              // smem reuse barrier

        // ---- load: threads 0-63 own i column e=t; 64-127 own j column ----
        if (t < TILE) {
            int e = t;
            float invi = g_inorm[b * NN + i0 + e];
#pragma unroll 8
            for (int c = 0; c < CF; c++) {
                float v = fb[c * NN + i0 + e] * invi;
                *(float2*)&fi_d[c][2 * e] = make_float2(v, v);
            }
            float4 si = g_st4[b * NN + i0 + e];
            float4 pi = g_pa4[b * NN + i0 + e];
            float2 qi = g_pb2[b * NN + i0 + e];
            *(float2*)&id_d[0][2 * e] = make_float2(si.x, si.x);
            *(float2*)&id_d[1][2 * e] = make_float2(si.y, si.y);
            *(float2*)&id_d[2][2 * e] = make_float2(si.z, si.z);
            *(float2*)&id_d[3][2 * e] = make_float2(pi.x, pi.x);
            *(float2*)&id_d[4][2 * e] = make_float2(pi.y, pi.y);
            *(float2*)&id_d[5][2 * e] = make_float2(pi.z, pi.z);
            *(float2*)&id_d[6][2 * e] = make_float2(pi.w, pi.w);
            *(float2*)&id_d[7][2 * e] = make_float2(qi.x, qi.x);
            *(float2*)&id_d[8][2 * e] = make_float2(qi.y, qi.y);
        } else {
            int e = t - TILE;
            float invj = g_inorm[b * NN + j0 + e];
#pragma unroll 8
            for (int c = 0; c < CF; c++)
                fj_s[c][e] = fb[c * NN + j0 + e] * invj;
            float4 sj = g_st4[b * NN + j0 + e];
            float4 pj = g_pa4[b * NN + j0 + e];
            float2 qj = g_pb2[b * NN + j0 + e];
            js_s[0][e] = -sj.x;
            js_s[1][e] = sj.y;
            js_s[2][e] = sj.z;
            js_s[3][e] = pj.x;
            js_s[4][e] = pj.y;
            js_s[5][e] = pj.z;
            js_s[6][e] = pj.w;
            js_s[7][e] = qj.x;
            js_s[8][e] = qj.y;
        }
        __syncthreads();

        // ---- gram: acc[ii][jp] packs (j = jx+2jp, jx+2jp+1) ----
        u64 acc[4][4];
#pragma unroll
        for (int a = 0; a < 4; a++)
#pragma unroll
            for (int c = 0; c < 4; c++) acc[a][c] = 0ull;

#pragma unroll 4
        for (int c = 0; c < CF; c++) {
            ulonglong2 a01 = *(const ulonglong2*)&fi_d[c][2 * iy];
            ulonglong2 a23 = *(const ulonglong2*)&fi_d[c][2 * iy + 4];
            ulonglong2 b03 = *(const ulonglong2*)&fj_s[c][jx];
            ulonglong2 b47 = *(const ulonglong2*)&fj_s[c][jx + 4];
            FMA2(acc[0][0], a01.x, b03.x, acc[0][0]);
            FMA2(acc[0][1], a01.x, b03.y, acc[0][1]);
            FMA2(acc[0][2], a01.x, b47.x, acc[0][2]);
            FMA2(acc[0][3], a01.x, b47.y, acc[0][3]);
            FMA2(acc[1][0], a01.y, b03.x, acc[1][0]);
            FMA2(acc[1][1], a01.y, b03.y, acc[1][1]);
            FMA2(acc[1][2], a01.y, b47.x, acc[1][2]);
            FMA2(acc[1][3], a01.y, b47.y, acc[1][3]);
            FMA2(acc[2][0], a23.x, b03.x, acc[2][0]);
            FMA2(acc[2][1], a23.x, b03.y, acc[2][1]);
            FMA2(acc[2][2], a23.x, b47.x, acc[2][2]);
            FMA2(acc[2][3], a23.x, b47.y, acc[2][3]);
            FMA2(acc[3][0], a23.y, b03.x, acc[3][0]);
            FMA2(acc[3][1], a23.y, b03.y, acc[3][1]);
            FMA2(acc[3][2], a23.y, b47.x, acc[3][2]);
            FMA2(acc[3][3], a23.y, b47.y, acc[3][3]);
        }

        // ---- epilogue ----
        float tpart = 0.0f;
#pragma unroll
        for (int ii = 0; ii < 4; ii++) {
            int i2 = 2 * (iy + ii);
            u64 mui = *(const u64*)&id_d[0][i2];
            u64 vi  = *(const u64*)&id_d[1][i2];
            u64 zi  = *(const u64*)&id_d[2][i2];
            u64 ei1 = *(const u64*)&id_d[3][i2];
            u64 ei2 = *(const u64*)&id_d[4][i2];
            u64 ei3 = *(const u64*)&id_d[5][i2];
            u64 si1 = *(const u64*)&id_d[6][i2];
            u64 si2 = *(const u64*)&id_d[7][i2];
            u64 si3 = *(const u64*)&id_d[8][i2];
#pragma unroll
            for (int jp = 0; jp < 4; jp++) {
                int j = jx + 2 * jp;
                u64 zj = *(const u64*)&js_s[2][j];
                u64 dmu, dmu2, tt, zs, d, ds, e2;
                ADD2(dmu, mui, *(const u64*)&js_s[0][j]);
                MUL2(dmu2, dmu, dmu);
                MUL2(tt, *(const u64*)&js_s[1][j], zi);
                FMA2(tt, vi, zj, tt);
                ADD2(zs, zi, zj);
                FMA2(tt, dmu2, zs, tt);
                FMA2(d, tt, C13, CHALF);
                FMA2(d, acc[ii][jp], CM23, d);
                MUL2(ds, d, d);
                MUL2(e2, ds, CEXP2);
                float eg0, eg1;
                UNPACK2(eg0, eg1, e2);
                float w0 = ex2f(eg0), w1 = ex2f(eg1);

                u64 n1, n2, n3, d1, d2, d3, t23, e12, den, num;
                MUL2(n1, ei1, *(const u64*)&js_s[3][j]);
                MUL2(n2, ei2, *(const u64*)&js_s[4][j]);
                MUL2(n3, ei3, *(const u64*)&js_s[5][j]);
                ADD2(d1, si1, *(const u64*)&js_s[6][j]);
                ADD2(d2, si2, *(const u64*)&js_s[7][j]);
                ADD2(d3, si3, *(const u64*)&js_s[8][j]);
                MUL2(t23, d2, d3);
                MUL2(e12, d1, d2);
                MUL2(den, e12, d3);
                MUL2(num, n1, t23);
                MUL2(t23, d1, d3);
                FMA2(num, n2, t23, num);
                FMA2(num, n3, e12, num);
                float num0, num1, den0, den1;
                UNPACK2(num0, num1, num);
                UNPACK2(den0, den1, den);
                tpart = fmaf(w0 * num0, rcpf(den0), tpart);
                tpart = fmaf(w1 * num1, rcpf(den1), tpart);
            }
        }
        if (ti != tj) tpart += tpart;   // off-diagonal tile pairs count twice
        part += tpart;
    }

    // ---- block reduction (4 warps) ----
#pragma unroll
    for (int o = 16; o; o >>= 1) part += __shfl_xor_sync(0xffffffffu, part, o);
    if (lane == 0) red_s[warp] = part;
    __syncthreads();

    if (t == 0) {
        float s = red_s[0] + red_s[1] + red_s[2] + red_s[3];
        g_partial[bid] = s;
        __threadfence();
        is_last = (atomicAdd(&g_count, 1) == NLAUNCH - 1);
    }
    __syncthreads();

    // ---- last block: deterministic final reduction ----
    if (is_last) {
        __shared__ double dred[4];
        double s = 0.0;
        for (int i = t; i < NLAUNCH; i += 128)
            s += (double)__ldcg(&g_partial[i]);
#pragma unroll
        for (int o = 16; o; o >>= 1)
            s += __longlong_as_double(
                 __shfl_xor_sync(0xffffffffu, __double_as_longlong(s), o));
        if (lane == 0) dred[warp] = s;
        __syncthreads();
        if (t == 0) {
            double total = dred[0] + dred[1] + dred[2] + dred[3];
            double score = total / ((double)BB * PCH * NN);
            out[0] = (float)(1.0 - score / (double)NN);
            g_count = 0;                // reset for next graph replay
        }
    }
}

extern "C" void kernel_launch(void* const* d_in, const int* in_sizes, int n_in,
                              void* d_out, int out_size) {
    const float* f = (const float*)d_in[0];
    const float* p = (const float*)d_in[1];
    precompute_kernel<<<(BB * NN + 63) / 64, 64>>>(f, p);
    pair_kernel<<<NLAUNCH, 128>>>(f, (float*)d_out);
}

// round 6
// speedup vs baseline: 1.4121x; 1.4121x over previous
#include <cuda_runtime.h>
#include <math.h>

#define NN      2304                    // 48*48
#define BB      2
#define CF      32
#define PCH     3
#define TILE    64
#define NT      (NN / TILE)             // 36
#define TPAIRS  (NT * (NT + 1) / 2)     // 666
#define NWORK   (BB * TPAIRS)           // 1332 tile-pairs
#define NLAUNCH 592                     // 148 SMs x 4 resident, single wave
#define NTRIPLE 148                     // bids < 148 do 3 tile-pairs, rest do 2
#define KP      2.8853900817779268f     // 4 / ln(4)
#define CEXP    -5.770780163555851f     // -4 * log2(e)
#define SQ2     1.4142135623730951f

// ---- scratch (no allocations allowed) ----
__device__ float4 g_st4[BB * NN];       // (mu, var, 0.25/var, -)
__device__ float4 g_pa4[BB * NN];       // (sqrt2*pE1..3, q1^2)
__device__ float2 g_pb2[BB * NN];       // (q2^2, q3^2)
__device__ float  g_inorm[BB * NN];     // rsqrt(||f||^2)
__device__ float  g_partial[NLAUNCH];
__device__ int    g_count = 0;

typedef unsigned long long u64;

// ---- packed f32x2 helpers (sm_103a) ----
#define FMA2(d, a, b, c) asm("fma.rn.f32x2 %0, %1, %2, %3;" \
    : "=l"(d) : "l"(a), "l"(b), "l"(c))
#define MUL2(d, a, b) asm("mul.rn.f32x2 %0, %1, %2;" \
    : "=l"(d) : "l"(a), "l"(b))
#define ADD2(d, a, b) asm("add.rn.f32x2 %0, %1, %2;" \
    : "=l"(d) : "l"(a), "l"(b))
#define PACK2(d, x) asm("mov.b64 %0, {%1, %1};" : "=l"(d) : "f"(x))
#define UNPACK2(lo, hi, v) asm("mov.b64 {%0, %1}, %2;" \
    : "=f"(lo), "=f"(hi) : "l"(v))

__device__ __forceinline__ float ex2f(float x) {
    float r; asm("ex2.approx.f32 %0, %1;" : "=f"(r) : "f"(x)); return r;
}
__device__ __forceinline__ float rcpf(float x) {
    float r; asm("rcp.approx.f32 %0, %1;" : "=f"(r) : "f"(x)); return r;
}

// ============================================================
// Kernel A: per-node stats + softmax-derived quantities
// ============================================================
__global__ void precompute_kernel(const float* __restrict__ f,
                                  const float* __restrict__ p) {
    int idx = blockIdx.x * 64 + threadIdx.x;
    if (idx >= BB * NN) return;
    int b = idx / NN;
    int n = idx - b * NN;

    const float* fb = f + (size_t)b * CF * NN + n;
    float s = 0.0f, ss = 0.0f;
#pragma unroll
    for (int c = 0; c < CF; c++) {
        float v = fb[c * NN];
        s += v;
        ss = fmaf(v, v, ss);
    }
    float mu  = s * (1.0f / CF);
    float var = (ss - s * mu) * (1.0f / (CF - 1));
    g_st4[idx]   = make_float4(mu, var, 0.25f / var, 0.0f);
    g_inorm[idx] = rsqrtf(ss);

    const float* pp = p + (size_t)b * 4 * NN + n;
    float e0 = __expf(pp[0]);
    float e1 = __expf(pp[NN]);
    float e2 = __expf(pp[2 * NN]);
    float e3 = __expf(pp[3 * NN]);
    float inv = __fdividef(1.0f, e0 + e1 + e2 + e3);
    float q1 = e1 * inv, q2 = e2 * inv, q3 = e3 * inv;
    float E1 = fmaf(KP * q1, __logf(q1), 1.0f);
    float E2 = fmaf(KP * q2, __logf(q2), 1.0f);
    float E3 = fmaf(KP * q3, __logf(q3), 1.0f);
    g_pa4[idx] = make_float4(SQ2 * q1 * E1, SQ2 * q2 * E2, SQ2 * q3 * E3, q1 * q1);
    g_pb2[idx] = make_float2(q2 * q2, q3 * q3);
}

// ============================================================
// Kernel B: 592 blocks x 128 thr (occ 4, single wave),
//   2-3 tile-pairs per block, 4i x 8j micro-tile,
//   f32x2 gram + interleaved-record f32x2 epilogue
//
// stat record (10 slots): 0:mu(i)/-mu(j) 1:v 2:z 3:pE1 4:pE2
//                         5:pE3 6:q1^2 7:q2^2 8:q3^2 9:pad
// ============================================================
__global__ void __launch_bounds__(128, 4) pair_kernel(const float* __restrict__ f,
                                                      float* __restrict__ out) {
    __shared__ __align__(16) float fi_d[CF][2 * TILE];   // i values duplicated
    __shared__ __align__(16) float fj_s[CF][TILE];
    __shared__ __align__(16) float id_q[TILE][20];       // i recs, dup: [i][2a+{0,1}]
    __shared__ __align__(16) float js_q[TILE / 2][20];   // j recs: [jj][2a+(j&1)]
    __shared__ float red_s[4];
    __shared__ int   is_last;

    int bid  = blockIdx.x;
    int t    = threadIdx.x;
    int lane = t & 31, warp = t >> 5;
    int tx = t & 7,  ty = t >> 3;      // 8 x 16 threads
    int jx = tx * 8, iy = ty * 4;

    u64 C13, CM23, CHALF, CEXP2;
    PACK2(C13,   (1.0f / 3.0f));
    PACK2(CM23, (-2.0f / 3.0f));
    PACK2(CHALF, 0.5f);
    PACK2(CEXP2, CEXP);

    float part = 0.0f;
    int nrep = (bid < NTRIPLE) ? 3 : 2;

    for (int rep = 0; rep < nrep; rep++) {
        int tp = bid + rep * NLAUNCH;          // unique in [0, 1332)
        int b  = tp / TPAIRS;
        int r  = tp - b * TPAIRS;
        int ti = 0;
        while (r >= NT - ti) { r -= NT - ti; ti++; }
        int tj = ti + r;
        int i0 = ti * TILE, j0 = tj * TILE;
        const float* fb = f + (size_t)b * CF * NN;

        if (rep) __syncthreads();              // smem reuse barrier

        // ---- loads: threads 0-63 fill i side, 64-127 fill j side ----
        if (t < TILE) {
            int e = t;
            float invi = g_inorm[b * NN + i0 + e];
#pragma unroll 8
            for (int c = 0; c < CF; c++) {
                float v = fb[c * NN + i0 + e] * invi;
                *(float2*)&fi_d[c][2 * e] = make_float2(v, v);
            }
            float4 si = g_st4[b * NN + i0 + e];
            float4 pi = g_pa4[b * NN + i0 + e];
            float2 qi = g_pb2[b * NN + i0 + e];
            float rec[10] = {si.x, si.y, si.z, pi.x, pi.y,
                             pi.z, pi.w, qi.x, qi.y, 0.0f};
#pragma unroll
            for (int a = 0; a < 10; a++)
                *(float2*)&id_q[e][2 * a] = make_float2(rec[a], rec[a]);
        } else {
            int e = t - TILE;
            float invj = g_inorm[b * NN + j0 + e];
#pragma unroll 8
            for (int c = 0; c < CF; c++)
                fj_s[c][e] = fb[c * NN + j0 + e] * invj;
            float4 sj = g_st4[b * NN + j0 + e];
            float4 pj = g_pa4[b * NN + j0 + e];
            float2 qj = g_pb2[b * NN + j0 + e];
            float rec[10] = {-sj.x, sj.y, sj.z, pj.x, pj.y,
                             pj.z, pj.w, qj.x, qj.y, 0.0f};
            int jj = e >> 1, lo = e & 1;
#pragma unroll
            for (int a = 0; a < 10; a++)
                js_q[jj][2 * a + lo] = rec[a];
        }
        __syncthreads();

        // ---- gram: acc[ii][jp] packs (j = jx+2jp, jx+2jp+1) ----
        u64 acc[4][4];
#pragma unroll
        for (int a = 0; a < 4; a++)
#pragma unroll
            for (int c = 0; c < 4; c++) acc[a][c] = 0ull;

#pragma unroll 4
        for (int c = 0; c < CF; c++) {
            ulonglong2 a01 = *(const ulonglong2*)&fi_d[c][2 * iy];
            ulonglong2 a23 = *(const ulonglong2*)&fi_d[c][2 * iy + 4];
            ulonglong2 b03 = *(const ulonglong2*)&fj_s[c][jx];
            ulonglong2 b47 = *(const ulonglong2*)&fj_s[c][jx + 4];
            FMA2(acc[0][0], a01.x, b03.x, acc[0][0]);
            FMA2(acc[0][1], a01.x, b03.y, acc[0][1]);
            FMA2(acc[0][2], a01.x, b47.x, acc[0][2]);
            FMA2(acc[0][3], a01.x, b47.y, acc[0][3]);
            FMA2(acc[1][0], a01.y, b03.x, acc[1][0]);
            FMA2(acc[1][1], a01.y, b03.y, acc[1][1]);
            FMA2(acc[1][2], a01.y, b47.x, acc[1][2]);
            FMA2(acc[1][3], a01.y, b47.y, acc[1][3]);
            FMA2(acc[2][0], a23.x, b03.x, acc[2][0]);
            FMA2(acc[2][1], a23.x, b03.y, acc[2][1]);
            FMA2(acc[2][2], a23.x, b47.x, acc[2][2]);
            FMA2(acc[2][3], a23.x, b47.y, acc[2][3]);
            FMA2(acc[3][0], a23.y, b03.x, acc[3][0]);
            FMA2(acc[3][1], a23.y, b03.y, acc[3][1]);
            FMA2(acc[3][2], a23.y, b47.x, acc[3][2]);
            FMA2(acc[3][3], a23.y, b47.y, acc[3][3]);
        }

        // ---- epilogue: hoist i record (5 LDS.128), stream j (5 LDS.128) ----
        float tpart = 0.0f;
#pragma unroll
        for (int ii = 0; ii < 4; ii++) {
            int i = iy + ii;
            ulonglong2 iA = *(const ulonglong2*)&id_q[i][0];   // mu, v
            ulonglong2 iB = *(const ulonglong2*)&id_q[i][4];   // z, pE1
            ulonglong2 iC = *(const ulonglong2*)&id_q[i][8];   // pE2, pE3
            ulonglong2 iD = *(const ulonglong2*)&id_q[i][12];  // q1, q2
            ulonglong2 iE = *(const ulonglong2*)&id_q[i][16];  // q3, pad
#pragma unroll
            for (int jp = 0; jp < 4; jp++) {
                int jj = tx * 4 + jp;
                ulonglong2 jA = *(const ulonglong2*)&js_q[jj][0];
                ulonglong2 jB = *(const ulonglong2*)&js_q[jj][4];
                ulonglong2 jC = *(const ulonglong2*)&js_q[jj][8];
                ulonglong2 jD = *(const ulonglong2*)&js_q[jj][12];
                ulonglong2 jE = *(const ulonglong2*)&js_q[jj][16];

                u64 dmu, dmu2, tt, zs, d, ds, e2;
                ADD2(dmu, iA.x, jA.x);           // mu_i - mu_j
                MUL2(dmu2, dmu, dmu);
                MUL2(tt, jA.y, iB.x);            // vj * zi
                FMA2(tt, iA.y, jB.x, tt);        // + vi * zj
                ADD2(zs, iB.x, jB.x);
                FMA2(tt, dmu2, zs, tt);
                FMA2(d, tt, C13, CHALF);
                FMA2(d, acc[ii][jp], CM23, d);
                MUL2(ds, d, d);
                MUL2(e2, ds, CEXP2);
                float eg0, eg1;
                UNPACK2(eg0, eg1, e2);
                float w0 = ex2f(eg0), w1 = ex2f(eg1);

                u64 n1, n2, n3, d1, d2, d3, t23, e12, den, num;
                MUL2(n1, iB.y, jB.y);            // pE1 products
                MUL2(n2, iC.x, jC.x);
                MUL2(n3, iC.y, jC.y);
                ADD2(d1, iD.x, jD.x);            // q^2 sums
                ADD2(d2, iD.y, jD.y);
                ADD2(d3, iE.x, jE.x);
                MUL2(t23, d2, d3);
                MUL2(e12, d1, d2);
                MUL2(den, e12, d3);
                MUL2(num, n1, t23);
                MUL2(t23, d1, d3);
                FMA2(num, n2, t23, num);
                FMA2(num, n3, e12, num);
                float num0, num1, den0, den1;
                UNPACK2(num0, num1, num);
                UNPACK2(den0, den1, den);
                tpart = fmaf(w0 * num0, rcpf(den0), tpart);
                tpart = fmaf(w1 * num1, rcpf(den1), tpart);
            }
        }
        if (ti != tj) tpart += tpart;      // off-diagonal tile pairs count twice
        part += tpart;
    }

    // ---- block reduction (4 warps) ----
#pragma unroll
    for (int o = 16; o; o >>= 1) part += __shfl_xor_sync(0xffffffffu, part, o);
    if (lane == 0) red_s[warp] = part;
    __syncthreads();

    if (t == 0) {
        float s = red_s[0] + red_s[1] + red_s[2] + red_s[3];
        g_partial[bid] = s;
        __threadfence();
        is_last = (atomicAdd(&g_count, 1) == NLAUNCH - 1);
    }
    __syncthreads();

    // ---- last block: deterministic final reduction ----
    if (is_last) {
        __shared__ double dred[4];
        double s = 0.0;
        for (int i = t; i < NLAUNCH; i += 128)
            s += (double)__ldcg(&g_partial[i]);
#pragma unroll
        for (int o = 16; o; o >>= 1)
            s += __longlong_as_double(
                 __shfl_xor_sync(0xffffffffu, __double_as_longlong(s), o));
        if (lane == 0) dred[warp] = s;
        __syncthreads();
        if (t == 0) {
            double total = dred[0] + dred[1] + dred[2] + dred[3];
            double score = total / ((double)BB * PCH * NN);
            out[0] = (float)(1.0 - score / (double)NN);
            g_count = 0;                   // reset for next graph replay
        }
    }
}

extern "C" void kernel_launch(void* const* d_in, const int* in_sizes, int n_in,
                              void* d_out, int out_size) {
    const float* f = (const float*)d_in[0];
    const float* p = (const float*)d_in[1];
    precompute_kernel<<<(BB * NN + 63) / 64, 64>>>(f, p);
    pair_kernel<<<NLAUNCH, 128>>>(f, (float*)d_out);
}

// round 7
// speedup vs baseline: 1.6946x; 1.2000x over previous
#include <cuda_runtime.h>
#include <math.h>

#define NN      2304                    // 48*48
#define BB      2
#define CF      32
#define PCH     3
#define TILE    64
#define NT      (NN / TILE)             // 36
#define TPAIRS  (NT * (NT + 1) / 2)     // 666
#define NWORK   (BB * TPAIRS)           // 1332 tile-pairs
#define NLAUNCH 444                     // 148 SMs x 3 resident, single wave
#define NREP    3                       // every block does exactly 3 tile-pairs
#define KP      2.8853900817779268f     // 4 / ln(4)
#define CEXP    -5.770780163555851f     // -4 * log2(e)
#define SQ2     1.4142135623730951f

// ---- scratch (no allocations allowed) ----
__device__ float4 g_st4[BB * NN];       // (mu, var, 0.25/var, -)
__device__ float4 g_pa4[BB * NN];       // (sqrt2*pE1..3, q1^2)
__device__ float2 g_pb2[BB * NN];       // (q2^2, q3^2)
__device__ float  g_inorm[BB * NN];     // rsqrt(||f||^2)
__device__ float  g_partial[NLAUNCH];
__device__ int    g_count = 0;

typedef unsigned long long u64;

// ---- packed f32x2 helpers (sm_103a) ----
#define FMA2(d, a, b, c) asm("fma.rn.f32x2 %0, %1, %2, %3;" \
    : "=l"(d) : "l"(a), "l"(b), "l"(c))
#define MUL2(d, a, b) asm("mul.rn.f32x2 %0, %1, %2;" \
    : "=l"(d) : "l"(a), "l"(b))
#define ADD2(d, a, b) asm("add.rn.f32x2 %0, %1, %2;" \
    : "=l"(d) : "l"(a), "l"(b))
#define PACK2(d, x) asm("mov.b64 %0, {%1, %1};" : "=l"(d) : "f"(x))
#define PACKW(d, lo, hi) asm("mov.b64 %0, {%1, %2};" : "=l"(d) : "f"(lo), "f"(hi))
#define UNPACK2(lo, hi, v) asm("mov.b64 {%0, %1}, %2;" \
    : "=f"(lo), "=f"(hi) : "l"(v))

__device__ __forceinline__ float ex2f(float x) {
    float r; asm("ex2.approx.f32 %0, %1;" : "=f"(r) : "f"(x)); return r;
}
__device__ __forceinline__ float rcpf(float x) {
    float r; asm("rcp.approx.f32 %0, %1;" : "=f"(r) : "f"(x)); return r;
}

// ============================================================
// Kernel A: per-node stats + softmax-derived quantities
// ============================================================
__global__ void precompute_kernel(const float* __restrict__ f,
                                  const float* __restrict__ p) {
    int idx = blockIdx.x * 64 + threadIdx.x;
    if (idx >= BB * NN) return;
    int b = idx / NN;
    int n = idx - b * NN;

    const float* fb = f + (size_t)b * CF * NN + n;
    float s = 0.0f, ss = 0.0f;
#pragma unroll
    for (int c = 0; c < CF; c++) {
        float v = fb[c * NN];
        s += v;
        ss = fmaf(v, v, ss);
    }
    float mu  = s * (1.0f / CF);
    float var = (ss - s * mu) * (1.0f / (CF - 1));
    g_st4[idx]   = make_float4(mu, var, 0.25f / var, 0.0f);
    g_inorm[idx] = rsqrtf(ss);

    const float* pp = p + (size_t)b * 4 * NN + n;
    float e0 = __expf(pp[0]);
    float e1 = __expf(pp[NN]);
    float e2 = __expf(pp[2 * NN]);
    float e3 = __expf(pp[3 * NN]);
    float inv = __fdividef(1.0f, e0 + e1 + e2 + e3);
    float q1 = e1 * inv, q2 = e2 * inv, q3 = e3 * inv;
    float E1 = fmaf(KP * q1, __logf(q1), 1.0f);
    float E2 = fmaf(KP * q2, __logf(q2), 1.0f);
    float E3 = fmaf(KP * q3, __logf(q3), 1.0f);
    g_pa4[idx] = make_float4(SQ2 * q1 * E1, SQ2 * q2 * E2, SQ2 * q3 * E3, q1 * q1);
    g_pb2[idx] = make_float2(q2 * q2, q3 * q3);
}

// ============================================================
// Kernel B: 444 blocks x 256 thr (occ 3, single wave, 3 reps),
//   4i x 4j micro-tile, f32x2 gram, PHASED f32x2 epilogue
// ============================================================
__global__ void __launch_bounds__(256, 3) pair_kernel(const float* __restrict__ f,
                                                      float* __restrict__ out) {
    __shared__ __align__(16) float fi_d[CF][2 * TILE];  // i values duplicated
    __shared__ __align__(16) float fj_s[CF][TILE];
    // i-side SoA, duplicated: 0:mu 1:v 2:z 3..5:pE 6..8:q^2
    __shared__ __align__(16) float id_d[9][2 * TILE];
    // j-side SoA, plain:      0:-mu 1:v 2:z 3..5:pE 6..8:q^2
    __shared__ __align__(16) float js_s[9][TILE];
    __shared__ float red_s[8];
    __shared__ int   is_last;

    int bid  = blockIdx.x;
    int t    = threadIdx.x;
    int lane = t & 31, warp = t >> 5;
    int tx = t & 15, ty = t >> 4;      // 16x16 threads, 4i x 4j each
    int jx = tx * 4, iy = ty * 4;

    u64 C13, CM23, CHALF, CEXP2;
    PACK2(C13,   (1.0f / 3.0f));
    PACK2(CM23, (-2.0f / 3.0f));
    PACK2(CHALF, 0.5f);
    PACK2(CEXP2, CEXP);

    float part = 0.0f;

#pragma unroll 1
    for (int rep = 0; rep < NREP; rep++) {
        int tp = bid + rep * NLAUNCH;          // unique in [0, 1332)
        int b  = tp / TPAIRS;
        int r  = tp - b * TPAIRS;
        int ti = 0;
        while (r >= NT - ti) { r -= NT - ti; ti++; }
        int tj = ti + r;
        int i0 = ti * TILE, j0 = tj * TILE;
        const float* fb = f + (size_t)b * CF * NN;

        if (rep) __syncthreads();              // smem reuse barrier

        // ---- loads (as R4): each thread owns column e = t&63 ----
        {
            int e  = t & (TILE - 1);
            int c0 = t >> 6;                   // 0..3
            float invi = g_inorm[b * NN + i0 + e];
            float invj = g_inorm[b * NN + j0 + e];
#pragma unroll
            for (int k = 0; k < CF / 4; k++) {
                int c = c0 + 4 * k;
                float vi = fb[c * NN + i0 + e] * invi;
                float vj = fb[c * NN + j0 + e] * invj;
                *(float2*)&fi_d[c][2 * e] = make_float2(vi, vi);
                fj_s[c][e] = vj;
            }
        }
        if (t < TILE) {
            int e = t;
            float4 si = g_st4[b * NN + i0 + e];
            float4 pi = g_pa4[b * NN + i0 + e];
            float2 qi = g_pb2[b * NN + i0 + e];
            *(float2*)&id_d[0][2 * e] = make_float2(si.x, si.x);
            *(float2*)&id_d[1][2 * e] = make_float2(si.y, si.y);
            *(float2*)&id_d[2][2 * e] = make_float2(si.z, si.z);
            *(float2*)&id_d[3][2 * e] = make_float2(pi.x, pi.x);
            *(float2*)&id_d[4][2 * e] = make_float2(pi.y, pi.y);
            *(float2*)&id_d[5][2 * e] = make_float2(pi.z, pi.z);
            *(float2*)&id_d[6][2 * e] = make_float2(pi.w, pi.w);
            *(float2*)&id_d[7][2 * e] = make_float2(qi.x, qi.x);
            *(float2*)&id_d[8][2 * e] = make_float2(qi.y, qi.y);
            float4 sj = g_st4[b * NN + j0 + e];
            float4 pj = g_pa4[b * NN + j0 + e];
            float2 qj = g_pb2[b * NN + j0 + e];
            js_s[0][e] = -sj.x;
            js_s[1][e] = sj.y;
            js_s[2][e] = sj.z;
            js_s[3][e] = pj.x;
            js_s[4][e] = pj.y;
            js_s[5][e] = pj.z;
            js_s[6][e] = pj.w;
            js_s[7][e] = qj.x;
            js_s[8][e] = qj.y;
        }
        __syncthreads();

        // ---- gram: acc[ii][jp] packs (j = jx+2jp, jx+2jp+1) ----
        u64 acc[4][2];
#pragma unroll
        for (int a = 0; a < 4; a++) { acc[a][0] = 0ull; acc[a][1] = 0ull; }

#pragma unroll 8
        for (int c = 0; c < CF; c++) {
            ulonglong2 a01 = *(const ulonglong2*)&fi_d[c][2 * iy];
            ulonglong2 a23 = *(const ulonglong2*)&fi_d[c][2 * iy + 4];
            ulonglong2 bb  = *(const ulonglong2*)&fj_s[c][jx];
            FMA2(acc[0][0], a01.x, bb.x, acc[0][0]);
            FMA2(acc[0][1], a01.x, bb.y, acc[0][1]);
            FMA2(acc[1][0], a01.y, bb.x, acc[1][0]);
            FMA2(acc[1][1], a01.y, bb.y, acc[1][1]);
            FMA2(acc[2][0], a23.x, bb.x, acc[2][0]);
            FMA2(acc[2][1], a23.x, bb.y, acc[2][1]);
            FMA2(acc[3][0], a23.y, bb.x, acc[3][0]);
            FMA2(acc[3][1], a23.y, bb.y, acc[3][1]);
        }

        // ==== PHASE 1: acc[ii][jp] := ds * CEXP (8 independent chains) ====
#pragma unroll
        for (int ii = 0; ii < 4; ii++) {
            int i2 = 2 * (iy + ii);
            u64 mui = *(const u64*)&id_d[0][i2];
            u64 vi  = *(const u64*)&id_d[1][i2];
            u64 zi  = *(const u64*)&id_d[2][i2];
#pragma unroll
            for (int jp = 0; jp < 2; jp++) {
                int j = jx + 2 * jp;
                u64 zj = *(const u64*)&js_s[2][j];
                u64 dmu, dmu2, tt, zs, d, ds;
                ADD2(dmu, mui, *(const u64*)&js_s[0][j]);
                MUL2(dmu2, dmu, dmu);
                MUL2(tt, *(const u64*)&js_s[1][j], zi);
                FMA2(tt, vi, zj, tt);
                ADD2(zs, zi, zj);
                FMA2(tt, dmu2, zs, tt);
                FMA2(d, tt, C13, CHALF);
                FMA2(d, acc[ii][jp], CM23, d);
                MUL2(ds, d, d);
                MUL2(acc[ii][jp], ds, CEXP2);
            }
        }

        // ==== PHASE 2: acc := packed w = ex2(acc) (16 MUFU burst) ====
#pragma unroll
        for (int ii = 0; ii < 4; ii++) {
#pragma unroll
            for (int jp = 0; jp < 2; jp++) {
                float e0, e1;
                UNPACK2(e0, e1, acc[ii][jp]);
                float w0 = ex2f(e0), w1 = ex2f(e1);
                PACKW(acc[ii][jp], w0, w1);
            }
        }

        // ==== PHASE 3: gs + accumulate (8 independent chains) ====
        float tpart = 0.0f;
#pragma unroll
        for (int ii = 0; ii < 4; ii++) {
            int i2 = 2 * (iy + ii);
            u64 ei1 = *(const u64*)&id_d[3][i2];
            u64 ei2 = *(const u64*)&id_d[4][i2];
            u64 ei3 = *(const u64*)&id_d[5][i2];
            u64 si1 = *(const u64*)&id_d[6][i2];
            u64 si2 = *(const u64*)&id_d[7][i2];
            u64 si3 = *(const u64*)&id_d[8][i2];
#pragma unroll
            for (int jp = 0; jp < 2; jp++) {
                int j = jx + 2 * jp;
                u64 n1, n2, n3, d1, d2, d3, t23, e12, den, num;
                MUL2(n1, ei1, *(const u64*)&js_s[3][j]);
                MUL2(n2, ei2, *(const u64*)&js_s[4][j]);
                MUL2(n3, ei3, *(const u64*)&js_s[5][j]);
                ADD2(d1, si1, *(const u64*)&js_s[6][j]);
                ADD2(d2, si2, *(const u64*)&js_s[7][j]);
                ADD2(d3, si3, *(const u64*)&js_s[8][j]);
                MUL2(t23, d2, d3);
                MUL2(e12, d1, d2);
                MUL2(den, e12, d3);
                MUL2(num, n1, t23);
                MUL2(t23, d1, d3);
                FMA2(num, n2, t23, num);
                FMA2(num, n3, e12, num);
                float num0, num1, den0, den1, w0, w1;
                UNPACK2(num0, num1, num);
                UNPACK2(den0, den1, den);
                UNPACK2(w0, w1, acc[ii][jp]);
                tpart = fmaf(w0 * num0, rcpf(den0), tpart);
                tpart = fmaf(w1 * num1, rcpf(den1), tpart);
            }
        }
        if (ti != tj) tpart += tpart;     // off-diagonal tile pairs count twice
        part += tpart;
    }

    // ---- block reduction (8 warps) ----
#pragma unroll
    for (int o = 16; o; o >>= 1) part += __shfl_xor_sync(0xffffffffu, part, o);
    if (lane == 0) red_s[warp] = part;
    __syncthreads();

    if (t == 0) {
        float s = 0.0f;
#pragma unroll
        for (int w = 0; w < 8; w++) s += red_s[w];
        g_partial[bid] = s;
        __threadfence();
        is_last = (atomicAdd(&g_count, 1) == NLAUNCH - 1);
    }
    __syncthreads();

    // ---- last block: deterministic final reduction ----
    if (is_last) {
        __shared__ double dred[8];
        double s = 0.0;
        for (int i = t; i < NLAUNCH; i += 256)
            s += (double)__ldcg(&g_partial[i]);
#pragma unroll
        for (int o = 16; o; o >>= 1)
            s += __longlong_as_double(
                 __shfl_xor_sync(0xffffffffu, __double_as_longlong(s), o));
        if (lane == 0) dred[warp] = s;
        __syncthreads();
        if (t == 0) {
            double total = 0.0;
#pragma unroll
            for (int w = 0; w < 8; w++) total += dred[w];
            double score = total / ((double)BB * PCH * NN);
            out[0] = (float)(1.0 - score / (double)NN);
            g_count = 0;                  // reset for next graph replay
        }
    }
}

extern "C" void kernel_launch(void* const* d_in, const int* in_sizes, int n_in,
                              void* d_out, int out_size) {
    const float* f = (const float*)d_in[0];
    const float* p = (const float*)d_in[1];
    precompute_kernel<<<(BB * NN + 63) / 64, 64>>>(f, p);
    pair_kernel<<<NLAUNCH, 256>>>(f, (float*)d_out);
}

// round 9
// speedup vs baseline: 2.1415x; 1.2637x over previous
#include <cuda_runtime.h>
#include <math.h>
#include <stdint.h>

#define NN      2304                    // 48*48
#define BB      2
#define CF      32
#define PCH     3
#define TILE    64
#define NT      (NN / TILE)             // 36
#define TPAIRS  (NT * (NT + 1) / 2)     // 666
#define NWORK   (BB * TPAIRS)           // 1332 tile-pairs
#define NLAUNCH 444                     // 148 SMs x 3 resident, single wave
#define NREP    3                       // every block does exactly 3 tile-pairs
#define KP      2.8853900817779268f     // 4 / ln(4)
#define CEXP    -5.770780163555851f     // -4 * log2(e)
#define SQ2     1.4142135623730951f
#define PITCH   36                      // u32 pitch, conflict-free frag loads

// ---- scratch (no allocations allowed) ----
__device__ float4 g_st4[BB * NN];       // (mu, var, 0.25/var, -)
__device__ float4 g_pa4[BB * NN];       // (sqrt2*pE1..3, q1^2)
__device__ float2 g_pb2[BB * NN];       // (q2^2, q3^2)
__device__ float  g_inorm[BB * NN];     // rsqrt(||f||^2)
__device__ float  g_partial[NLAUNCH];
__device__ int    g_count = 0;

typedef unsigned long long u64;
typedef unsigned int u32;

// ---- packed f32x2 helpers (sm_103a) ----
#define FMA2(d, a, b, c) asm("fma.rn.f32x2 %0, %1, %2, %3;" \
    : "=l"(d) : "l"(a), "l"(b), "l"(c))
#define MUL2(d, a, b) asm("mul.rn.f32x2 %0, %1, %2;" : "=l"(d) : "l"(a), "l"(b))
#define ADD2(d, a, b) asm("add.rn.f32x2 %0, %1, %2;" : "=l"(d) : "l"(a), "l"(b))
#define PACK2(d, x) asm("mov.b64 %0, {%1, %1};" : "=l"(d) : "f"(x))
#define PACKW(d, lo, hi) asm("mov.b64 %0, {%1, %2};" : "=l"(d) : "f"(lo), "f"(hi))
#define UNPACK2(lo, hi, v) asm("mov.b64 {%0, %1}, %2;" : "=f"(lo), "=f"(hi) : "l"(v))
#define CVT_TF32(d, x) asm("cvt.rna.tf32.f32 %0, %1;" : "=r"(d) : "f"(x))

__device__ __forceinline__ float ex2f(float x) {
    float r; asm("ex2.approx.f32 %0, %1;" : "=f"(r) : "f"(x)); return r;
}
__device__ __forceinline__ float rcpf(float x) {
    float r; asm("rcp.approx.f32 %0, %1;" : "=f"(r) : "f"(x)); return r;
}

// m16n8k8 tf32 mma, D += A*B  (row.col)
#define MMA_TF32(d, a0, a1, a2, a3, b0, b1) asm volatile( \
    "mma.sync.aligned.m16n8k8.row.col.f32.tf32.tf32.f32 " \
    "{%0,%1,%2,%3}, {%4,%5,%6,%7}, {%8,%9}, {%0,%1,%2,%3};" \
    : "+f"((d)[0]), "+f"((d)[1]), "+f"((d)[2]), "+f"((d)[3]) \
    : "r"(a0), "r"(a1), "r"(a2), "r"(a3), "r"(b0), "r"(b1))

// ============================================================
// Kernel A: per-node stats + softmax-derived quantities
// ============================================================
__global__ void precompute_kernel(const float* __restrict__ f,
                                  const float* __restrict__ p) {
    int idx = blockIdx.x * 64 + threadIdx.x;
    if (idx >= BB * NN) return;
    int b = idx / NN;
    int n = idx - b * NN;

    const float* fb = f + (size_t)b * CF * NN + n;
    float s = 0.0f, ss = 0.0f;
#pragma unroll
    for (int c = 0; c < CF; c++) {
        float v = fb[c * NN];
        s += v;
        ss = fmaf(v, v, ss);
    }
    float mu  = s * (1.0f / CF);
    float var = (ss - s * mu) * (1.0f / (CF - 1));
    g_st4[idx]   = make_float4(mu, var, 0.25f / var, 0.0f);
    g_inorm[idx] = rsqrtf(ss);

    const float* pp = p + (size_t)b * 4 * NN + n;
    float e0 = __expf(pp[0]);
    float e1 = __expf(pp[NN]);
    float e2 = __expf(pp[2 * NN]);
    float e3 = __expf(pp[3 * NN]);
    float inv = __fdividef(1.0f, e0 + e1 + e2 + e3);
    float q1 = e1 * inv, q2 = e2 * inv, q3 = e3 * inv;
    float E1 = fmaf(KP * q1, __logf(q1), 1.0f);
    float E2 = fmaf(KP * q2, __logf(q2), 1.0f);
    float E3 = fmaf(KP * q3, __logf(q3), 1.0f);
    g_pa4[idx] = make_float4(SQ2 * q1 * E1, SQ2 * q2 * E2, SQ2 * q3 * E3, q1 * q1);
    g_pb2[idx] = make_float2(q2 * q2, q3 * q3);
}

// ============================================================
// Kernel B: 444 blocks x 256 thr (occ 3, single wave, 3 reps)
//   gram via tf32 mma.sync (tensor pipe), f32x2 epilogue
//   warps: 4 (i, 16 rows each) x 2 (j, 32 cols each)
// ============================================================
__global__ void __launch_bounds__(256, 3) pair_kernel(const float* __restrict__ f,
                                                      float* __restrict__ out) {
    __shared__ u32   as32[TILE][PITCH];     // i-side tf32, [i][k]
    __shared__ u32   bs32[TILE][PITCH];     // j-side tf32, [j][k]
    __shared__ float id_d[9][2 * TILE];     // i stats, lane-duplicated
    __shared__ float js_s[9][TILE];         // j stats (0 = -mu)
    __shared__ float red_s[8];
    __shared__ int   is_last;

    int bid  = blockIdx.x;
    int t    = threadIdx.x;
    int lane = t & 31, warp = t >> 5;
    int g    = lane >> 2, tig = lane & 3;   // mma fragment coords
    int ar0  = (warp & 3) * 16 + g;         // this thread's first i row
    int jb   = (warp >> 2) * 32;            // warp's j block

    u64 C13, CM23, CHALF, CEXP2;
    PACK2(C13,   (1.0f / 3.0f));
    PACK2(CM23, (-2.0f / 3.0f));
    PACK2(CHALF, 0.5f);
    PACK2(CEXP2, CEXP);

    float part = 0.0f;

#pragma unroll 1
    for (int rep = 0; rep < NREP; rep++) {
        int tp = bid + rep * NLAUNCH;          // unique in [0, 1332)
        int b  = tp / TPAIRS;
        int r  = tp - b * TPAIRS;
        int ti = 0;
        while (r >= NT - ti) { r -= NT - ti; ti++; }
        int tj = ti + r;
        int i0 = ti * TILE, j0 = tj * TILE;
        int bNN = b * NN;
        const float* fb = f + (size_t)b * CF * NN;

        if (rep) __syncthreads();              // smem reuse barrier

        // ---- stage tf32 tiles: thread owns row e = t&63, k = t>>6 (+4n) ----
        {
            int e  = t & (TILE - 1);
            int c0 = t >> 6;                   // 0..3
            float invi = g_inorm[bNN + i0 + e];
            float invj = g_inorm[bNN + j0 + e];
#pragma unroll
            for (int k = 0; k < CF / 4; k++) {
                int c = c0 + 4 * k;
                float vi = fb[c * NN + i0 + e] * invi;
                float vj = fb[c * NN + j0 + e] * invj;
                u32 ta, tb;
                CVT_TF32(ta, vi);
                CVT_TF32(tb, vj);
                as32[e][c] = ta;
                bs32[e][c] = tb;
            }
        }
        if (t < TILE) {
            int e = t;
            float4 si = g_st4[bNN + i0 + e];
            float4 pi = g_pa4[bNN + i0 + e];
            float2 qi = g_pb2[bNN + i0 + e];
            *(float2*)&id_d[0][2 * e] = make_float2(si.x, si.x);
            *(float2*)&id_d[1][2 * e] = make_float2(si.y, si.y);
            *(float2*)&id_d[2][2 * e] = make_float2(si.z, si.z);
            *(float2*)&id_d[3][2 * e] = make_float2(pi.x, pi.x);
            *(float2*)&id_d[4][2 * e] = make_float2(pi.y, pi.y);
            *(float2*)&id_d[5][2 * e] = make_float2(pi.z, pi.z);
            *(float2*)&id_d[6][2 * e] = make_float2(pi.w, pi.w);
            *(float2*)&id_d[7][2 * e] = make_float2(qi.x, qi.x);
            *(float2*)&id_d[8][2 * e] = make_float2(qi.y, qi.y);
            float4 sj = g_st4[bNN + j0 + e];
            float4 pj = g_pa4[bNN + j0 + e];
            float2 qj = g_pb2[bNN + j0 + e];
            js_s[0][e] = -sj.x;
            js_s[1][e] = sj.y;
            js_s[2][e] = sj.z;
            js_s[3][e] = pj.x;
            js_s[4][e] = pj.y;
            js_s[5][e] = pj.z;
            js_s[6][e] = pj.w;
            js_s[7][e] = qj.x;
            js_s[8][e] = qj.y;
        }
        __syncthreads();

        // ---- gram via mma.sync: warp tile 16i x 32j, K=32 (4 k-steps) ----
        float acc[4][4];                       // [n-tile][c], c: (r0,2tig),(r0,2tig+1),(r1,..)
#pragma unroll
        for (int n = 0; n < 4; n++)
#pragma unroll
            for (int c = 0; c < 4; c++) acc[n][c] = 0.0f;

#pragma unroll
        for (int kk = 0; kk < 4; kk++) {
            int kb = 8 * kk + tig;
            u32 a0 = as32[ar0][kb];
            u32 a1 = as32[ar0 + 8][kb];
            u32 a2 = as32[ar0][kb + 4];
            u32 a3 = as32[ar0 + 8][kb + 4];
#pragma unroll
            for (int n = 0; n < 4; n++) {
                int bc = jb + 8 * n + g;
                u32 b0 = bs32[bc][kb];
                u32 b1 = bs32[bc][kb + 4];
                MMA_TF32(acc[n], a0, a1, a2, a3, b0, b1);
            }
        }

        // ---- epilogue: 2 i-rows x 4 packed (j,j+1) pairs ----
        float tpart = 0.0f;
#pragma unroll
        for (int h = 0; h < 2; h++) {
            int i2 = 2 * (ar0 + 8 * h);
            u64 mui = *(const u64*)&id_d[0][i2];
            u64 vi  = *(const u64*)&id_d[1][i2];
            u64 zi  = *(const u64*)&id_d[2][i2];
            u64 ei1 = *(const u64*)&id_d[3][i2];
            u64 ei2 = *(const u64*)&id_d[4][i2];
            u64 ei3 = *(const u64*)&id_d[5][i2];
            u64 si1 = *(const u64*)&id_d[6][i2];
            u64 si2 = *(const u64*)&id_d[7][i2];
            u64 si3 = *(const u64*)&id_d[8][i2];
#pragma unroll
            for (int n = 0; n < 4; n++) {
                int j = jb + 8 * n + 2 * tig;
                u64 gp;
                PACKW(gp, acc[n][2 * h], acc[n][2 * h + 1]);
                u64 zj = *(const u64*)&js_s[2][j];
                u64 dmu, dmu2, tt, zs, d, ds, e2;
                ADD2(dmu, mui, *(const u64*)&js_s[0][j]);
                MUL2(dmu2, dmu, dmu);
                MUL2(tt, *(const u64*)&js_s[1][j], zi);
                FMA2(tt, vi, zj, tt);
                ADD2(zs, zi, zj);
                FMA2(tt, dmu2, zs, tt);
                FMA2(d, tt, C13, CHALF);
                FMA2(d, gp, CM23, d);
                MUL2(ds, d, d);
                MUL2(e2, ds, CEXP2);
                float eg0, eg1;
                UNPACK2(eg0, eg1, e2);
                float w0 = ex2f(eg0), w1 = ex2f(eg1);

                u64 n1, n2, n3, d1, d2, d3, t23, e12, den, num;
                MUL2(n1, ei1, *(const u64*)&js_s[3][j]);
                MUL2(n2, ei2, *(const u64*)&js_s[4][j]);
                MUL2(n3, ei3, *(const u64*)&js_s[5][j]);
                ADD2(d1, si1, *(const u64*)&js_s[6][j]);
                ADD2(d2, si2, *(const u64*)&js_s[7][j]);
                ADD2(d3, si3, *(const u64*)&js_s[8][j]);
                MUL2(t23, d2, d3);
                MUL2(e12, d1, d2);
                MUL2(den, e12, d3);
                MUL2(num, n1, t23);
                MUL2(t23, d1, d3);
                FMA2(num, n2, t23, num);
                FMA2(num, n3, e12, num);
                float num0, num1, den0, den1;
                UNPACK2(num0, num1, num);
                UNPACK2(den0, den1, den);
                tpart = fmaf(w0 * num0, rcpf(den0), tpart);
                tpart = fmaf(w1 * num1, rcpf(den1), tpart);
            }
        }
        if (ti != tj) tpart += tpart;     // off-diagonal tile pairs count twice
        part += tpart;
    }

    // ---- block reduction (8 warps) ----
#pragma unroll
    for (int o = 16; o; o >>= 1) part += __shfl_xor_sync(0xffffffffu, part, o);
    if (lane == 0) red_s[warp] = part;
    __syncthreads();

    if (t == 0) {
        float s = 0.0f;
#pragma unroll
        for (int w = 0; w < 8; w++) s += red_s[w];
        g_partial[bid] = s;
        __threadfence();
        is_last = (atomicAdd(&g_count, 1) == NLAUNCH - 1);
    }
    __syncthreads();

    // ---- last block: deterministic final reduction ----
    if (is_last) {
        __shared__ double dred[8];
        double s = 0.0;
        for (int i = t; i < NLAUNCH; i += 256)
            s += (double)__ldcg(&g_partial[i]);
#pragma unroll
        for (int o = 16; o; o >>= 1)
            s += __longlong_as_double(
                 __shfl_xor_sync(0xffffffffu, __double_as_longlong(s), o));
        if (lane == 0) dred[warp] = s;
        __syncthreads();
        if (t == 0) {
            double total = 0.0;
#pragma unroll
            for (int w = 0; w < 8; w++) total += dred[w];
            double score = total / ((double)BB * PCH * NN);
            out[0] = (float)(1.0 - score / (double)NN);
            g_count = 0;                  // reset for next graph replay
        }
    }
}

extern "C" void kernel_launch(void* const* d_in, const int* in_sizes, int n_in,
                              void* d_out, int out_size) {
    const float* f = (const float*)d_in[0];
    const float* p = (const float*)d_in[1];
    precompute_kernel<<<(BB * NN + 63) / 64, 64>>>(f, p);
    pair_kernel<<<NLAUNCH, 256>>>(f, (float*)d_out);
}

// round 10
// speedup vs baseline: 2.2303x; 1.0415x over previous
#include <cuda_runtime.h>
#include <math.h>
#include <stdint.h>

#define NN      2304                    // 48*48
#define BB      2
#define CF      32
#define PCH     3
#define TILE    64
#define NT      (NN / TILE)             // 36
#define TPAIRS  (NT * (NT + 1) / 2)     // 666
#define NWORK   (BB * TPAIRS)           // 1332 tile-pairs
#define NLAUNCH 444                     // 148 SMs x 3 resident, single wave
#define NREP    3                       // every block does exactly 3 tile-pairs
#define KP      2.8853900817779268f     // 4 / ln(4)
#define CEXP    -5.770780163555851f     // -4 * log2(e)
#define SQ2     1.4142135623730951f
#define PITCH   36                      // u32 pitch, conflict-free frag loads

// ---- scratch (no allocations allowed) ----
__device__ float4   g_st4[BB * NN];     // (mu, var, 0.25/var, -mu)
__device__ float4   g_pa4[BB * NN];     // (sqrt2*pE1..3, q1^2)
__device__ float2   g_pb2[BB * NN];     // (q2^2, q3^2)
__device__ __align__(16) unsigned int g_ftf[BB * NN * CF]; // normalized tf32, node-major
__device__ float    g_partial[NLAUNCH];
__device__ int      g_count = 0;

typedef unsigned long long u64;
typedef unsigned int u32;

// ---- packed f32x2 helpers (sm_103a) ----
#define FMA2(d, a, b, c) asm("fma.rn.f32x2 %0, %1, %2, %3;" \
    : "=l"(d) : "l"(a), "l"(b), "l"(c))
#define MUL2(d, a, b) asm("mul.rn.f32x2 %0, %1, %2;" : "=l"(d) : "l"(a), "l"(b))
#define ADD2(d, a, b) asm("add.rn.f32x2 %0, %1, %2;" : "=l"(d) : "l"(a), "l"(b))
#define PACK2(d, x) asm("mov.b64 %0, {%1, %1};" : "=l"(d) : "f"(x))
#define PACKW(d, lo, hi) asm("mov.b64 %0, {%1, %2};" : "=l"(d) : "f"(lo), "f"(hi))
#define UNPACK2(lo, hi, v) asm("mov.b64 {%0, %1}, %2;" : "=f"(lo), "=f"(hi) : "l"(v))
#define CVT_TF32(d, x) asm("cvt.rna.tf32.f32 %0, %1;" : "=r"(d) : "f"(x))

__device__ __forceinline__ float ex2f(float x) {
    float r; asm("ex2.approx.f32 %0, %1;" : "=f"(r) : "f"(x)); return r;
}
__device__ __forceinline__ float rcpf(float x) {
    float r; asm("rcp.approx.f32 %0, %1;" : "=f"(r) : "f"(x)); return r;
}
__device__ __forceinline__ u32 smem_u32(const void* p) {
    u32 a; asm("{ .reg .u64 t; cvta.to.shared.u64 t, %1; cvt.u32.u64 %0, t; }"
               : "=r"(a) : "l"(p));
    return a;
}
#define CP_ASYNC16(daddr, gp) asm volatile( \
    "cp.async.cg.shared.global [%0], [%1], 16;" :: "r"(daddr), "l"(gp) : "memory")
#define CP_COMMIT() asm volatile("cp.async.commit_group;" ::: "memory")
#define CP_WAIT(n)  asm volatile("cp.async.wait_group %0;" :: "n"(n) : "memory")

// m16n8k8 tf32 mma, D += A*B  (row.col)
#define MMA_TF32(d, a0, a1, a2, a3, b0, b1) asm volatile( \
    "mma.sync.aligned.m16n8k8.row.col.f32.tf32.tf32.f32 " \
    "{%0,%1,%2,%3}, {%4,%5,%6,%7}, {%8,%9}, {%0,%1,%2,%3};" \
    : "+f"((d)[0]), "+f"((d)[1]), "+f"((d)[2]), "+f"((d)[3]) \
    : "r"(a0), "r"(a1), "r"(a2), "r"(a3), "r"(b0), "r"(b1))

// ============================================================
// Kernel A: stats + softmax + normalized tf32 feature rows
// ============================================================
__global__ void precompute_kernel(const float* __restrict__ f,
                                  const float* __restrict__ p) {
    int idx = blockIdx.x * 64 + threadIdx.x;
    if (idx >= BB * NN) return;
    int b = idx / NN;
    int n = idx - b * NN;

    const float* fb = f + (size_t)b * CF * NN + n;
    float v[CF];
    float s = 0.0f, ss = 0.0f;
#pragma unroll
    for (int c = 0; c < CF; c++) {
        v[c] = fb[c * NN];
        s += v[c];
        ss = fmaf(v[c], v[c], ss);
    }
    float mu  = s * (1.0f / CF);
    float var = (ss - s * mu) * (1.0f / (CF - 1));
    g_st4[idx] = make_float4(mu, var, 0.25f / var, -mu);

    float inorm = rsqrtf(ss);
    u32* frow = &g_ftf[idx * CF];
#pragma unroll
    for (int c4 = 0; c4 < CF / 4; c4++) {
        uint4 o;
        CVT_TF32(o.x, v[4 * c4 + 0] * inorm);
        CVT_TF32(o.y, v[4 * c4 + 1] * inorm);
        CVT_TF32(o.z, v[4 * c4 + 2] * inorm);
        CVT_TF32(o.w, v[4 * c4 + 3] * inorm);
        *(uint4*)&frow[4 * c4] = o;
    }

    const float* pp = p + (size_t)b * 4 * NN + n;
    float e0 = __expf(pp[0]);
    float e1 = __expf(pp[NN]);
    float e2 = __expf(pp[2 * NN]);
    float e3 = __expf(pp[3 * NN]);
    float inv = __fdividef(1.0f, e0 + e1 + e2 + e3);
    float q1 = e1 * inv, q2 = e2 * inv, q3 = e3 * inv;
    float E1 = fmaf(KP * q1, __logf(q1), 1.0f);
    float E2 = fmaf(KP * q2, __logf(q2), 1.0f);
    float E3 = fmaf(KP * q3, __logf(q3), 1.0f);
    g_pa4[idx] = make_float4(SQ2 * q1 * E1, SQ2 * q2 * E2, SQ2 * q3 * E3, q1 * q1);
    g_pb2[idx] = make_float2(q2 * q2, q3 * q3);
}

// ============================================================
// Kernel B: 444 blocks x 256 thr (occ 3, single wave, 3 reps)
//   cp.async double-buffered tf32 tiles, mma.sync gram,
//   record-packed f32x2 epilogue
// ============================================================
__global__ void __launch_bounds__(256, 3) pair_kernel(float* __restrict__ out) {
    __shared__ __align__(16) u32 ftile[2][2][TILE][PITCH];  // [buf][side][row][k]
    __shared__ __align__(16) u64 id_q[TILE][10];            // i recs (dup pairs)
    __shared__ __align__(16) u64 js_q[TILE / 2][10];        // j recs (j, j+1)
    __shared__ float red_s[8];
    __shared__ int   is_last;

    int bid  = blockIdx.x;
    int t    = threadIdx.x;
    int lane = t & 31, warp = t >> 5;
    int g    = lane >> 2, tig = lane & 3;   // mma fragment coords
    int ar0  = (warp & 3) * 16 + g;         // first i row of this thread
    int jb   = (warp >> 2) * 32;            // warp's j block

    // decode rep -> (b, i0, j0, offdiag) ---------------------------------
    int I0[NREP], J0[NREP], BN[NREP], OD[NREP];
#pragma unroll
    for (int rep = 0; rep < NREP; rep++) {
        int tp = bid + rep * NLAUNCH;
        int b  = tp / TPAIRS;
        int r  = tp - b * TPAIRS;
        int ti = 0;
        while (r >= NT - ti) { r -= NT - ti; ti++; }
        int tj = ti + r;
        BN[rep] = b * NN;
        I0[rep] = ti * TILE;
        J0[rep] = tj * TILE;
        OD[rep] = (ti != tj);
    }

    u64 C13, CM23, CHALF, CEXP2;
    PACK2(C13,   (1.0f / 3.0f));
    PACK2(CM23, (-2.0f / 3.0f));
    PACK2(CHALF, 0.5f);
    PACK2(CEXP2, CEXP);

    // cp.async chunk mapping: 1024 chunks of 16B, 4 per thread
    int seg  = t & 7;                       // 16B segment within row
    int row4 = (t >> 3) & 63;               // row
    int side4 = t >> 9;                     // always 0 for t<512; use k loop
    (void)side4;

    // prologue: stage f tiles for rep 0 into buf 0
    {
#pragma unroll
        for (int k = 0; k < 4; k++) {
            int ch   = t + 256 * k;         // 0..1023
            int sg   = ch & 7;
            int rw   = (ch >> 3) & 63;
            int sd   = ch >> 9;
            int base = sd ? J0[0] : I0[0];
            const u32* gp = &g_ftf[(BN[0] + base + rw) * CF + sg * 4];
            CP_ASYNC16(smem_u32(&ftile[0][sd][rw][sg * 4]), gp);
        }
        CP_COMMIT();
    }
    (void)seg; (void)row4;

    float part = 0.0f;

#pragma unroll 1
    for (int rep = 0; rep < NREP; rep++) {
        int cur = rep & 1;
        int bNN = BN[rep], i0 = I0[rep], j0 = J0[rep];

        __syncthreads();                    // prev compute done; stat bufs free

        // ---- stage stats for cur (single-buffered, pure copy) ----
        if (t < TILE) {
            int e = t;
            float4 si = g_st4[bNN + i0 + e];
            float4 pi = g_pa4[bNN + i0 + e];
            float2 qi = g_pb2[bNN + i0 + e];
            float rec[9] = {si.x, si.y, si.z, pi.x, pi.y, pi.z, pi.w, qi.x, qi.y};
            u64* dst = id_q[e];
#pragma unroll
            for (int a = 0; a < 9; a++) {
                u64 dv; PACK2(dv, rec[a]);
                dst[a] = dv;
            }
        } else if (t < 2 * TILE) {
            int e = t - TILE;
            float4 sj = g_st4[bNN + j0 + e];
            float4 pj = g_pa4[bNN + j0 + e];
            float2 qj = g_pb2[bNN + j0 + e];
            float rec[9] = {sj.w, sj.y, sj.z, pj.x, pj.y, pj.z, pj.w, qj.x, qj.y};
            float* dst = (float*)js_q[e >> 1] + (e & 1);
#pragma unroll
            for (int a = 0; a < 9; a++) dst[2 * a] = rec[a];
        }

        // ---- stage f tiles for rep+1 into the other buffer ----
        if (rep + 1 < NREP) {
#pragma unroll
            for (int k = 0; k < 4; k++) {
                int ch   = t + 256 * k;
                int sg   = ch & 7;
                int rw   = (ch >> 3) & 63;
                int sd   = ch >> 9;
                int base = sd ? J0[rep + 1] : I0[rep + 1];
                const u32* gp = &g_ftf[(BN[rep + 1] + base + rw) * CF + sg * 4];
                CP_ASYNC16(smem_u32(&ftile[1 - cur][sd][rw][sg * 4]), gp);
            }
            CP_COMMIT();
            CP_WAIT(1);                     // cur's group done; next may fly
        } else {
            CP_WAIT(0);
        }
        __syncthreads();                    // staging visible

        // ---- gram via mma.sync: warp tile 16i x 32j, K=32 ----
        const u32 (*as32)[PITCH] = ftile[cur][0];
        const u32 (*bs32)[PITCH] = ftile[cur][1];
        float acc[4][4];
#pragma unroll
        for (int n = 0; n < 4; n++)
#pragma unroll
            for (int c = 0; c < 4; c++) acc[n][c] = 0.0f;

#pragma unroll
        for (int kk = 0; kk < 4; kk++) {
            int kb = 8 * kk + tig;
            u32 a0 = as32[ar0][kb];
            u32 a1 = as32[ar0 + 8][kb];
            u32 a2 = as32[ar0][kb + 4];
            u32 a3 = as32[ar0 + 8][kb + 4];
#pragma unroll
            for (int n = 0; n < 4; n++) {
                int bc = jb + 8 * n + g;
                u32 b0 = bs32[bc][kb];
                u32 b1 = bs32[bc][kb + 4];
                MMA_TF32(acc[n], a0, a1, a2, a3, b0, b1);
            }
        }

        // ---- epilogue: record loads, f32x2 math ----
        float tpart = 0.0f;
#pragma unroll
        for (int h = 0; h < 2; h++) {
            const u64* irec = id_q[ar0 + 8 * h];
            ulonglong2 iA = *(const ulonglong2*)&irec[0];   // mu, v
            ulonglong2 iB = *(const ulonglong2*)&irec[2];   // z, pE1
            ulonglong2 iC = *(const ulonglong2*)&irec[4];   // pE2, pE3
            ulonglong2 iD = *(const ulonglong2*)&irec[6];   // q1, q2
            u64        iE = irec[8];                        // q3
#pragma unroll
            for (int n = 0; n < 4; n++) {
                const u64* jrec = js_q[(jb >> 1) + 4 * n + tig];
                ulonglong2 jA = *(const ulonglong2*)&jrec[0];
                ulonglong2 jB = *(const ulonglong2*)&jrec[2];
                ulonglong2 jC = *(const ulonglong2*)&jrec[4];
                ulonglong2 jD = *(const ulonglong2*)&jrec[6];
                u64        jE = jrec[8];

                u64 gp;
                PACKW(gp, acc[n][2 * h], acc[n][2 * h + 1]);
                u64 dmu, dmu2, tt, zs, d, ds, e2;
                ADD2(dmu, iA.x, jA.x);          // mu_i + (-mu_j)
                MUL2(dmu2, dmu, dmu);
                MUL2(tt, jA.y, iB.x);           // vj * zi
                FMA2(tt, iA.y, jB.x, tt);       // + vi * zj
                ADD2(zs, iB.x, jB.x);
                FMA2(tt, dmu2, zs, tt);
                FMA2(d, tt, C13, CHALF);
                FMA2(d, gp, CM23, d);
                MUL2(ds, d, d);
                MUL2(e2, ds, CEXP2);
                float eg0, eg1;
                UNPACK2(eg0, eg1, e2);
                float w0 = ex2f(eg0), w1 = ex2f(eg1);

                u64 n1, n2, n3, d1, d2, d3, t23, e12, den, num;
                MUL2(n1, iB.y, jB.y);
                MUL2(n2, iC.x, jC.x);
                MUL2(n3, iC.y, jC.y);
                ADD2(d1, iD.x, jD.x);
                ADD2(d2, iD.y, jD.y);
                ADD2(d3, iE, jE);
                MUL2(t23, d2, d3);
                MUL2(e12, d1, d2);
                MUL2(den, e12, d3);
                MUL2(num, n1, t23);
                MUL2(t23, d1, d3);
                FMA2(num, n2, t23, num);
                FMA2(num, n3, e12, num);
                float num0, num1, den0, den1;
                UNPACK2(num0, num1, num);
                UNPACK2(den0, den1, den);
                tpart = fmaf(w0 * num0, rcpf(den0), tpart);
                tpart = fmaf(w1 * num1, rcpf(den1), tpart);
            }
        }
        if (OD[rep]) tpart += tpart;       // off-diagonal tile pairs count twice
        part += tpart;
    }

    // ---- block reduction (8 warps) ----
#pragma unroll
    for (int o = 16; o; o >>= 1) part += __shfl_xor_sync(0xffffffffu, part, o);
    if (lane == 0) red_s[warp] = part;
    __syncthreads();

    if (t == 0) {
        float s = 0.0f;
#pragma unroll
        for (int w = 0; w < 8; w++) s += red_s[w];
        g_partial[bid] = s;
        __threadfence();
        is_last = (atomicAdd(&g_count, 1) == NLAUNCH - 1);
    }
    __syncthreads();

    // ---- last block: deterministic final reduction ----
    if (is_last) {
        __shared__ double dred[8];
        double s = 0.0;
        for (int i = t; i < NLAUNCH; i += 256)
            s += (double)__ldcg(&g_partial[i]);
#pragma unroll
        for (int o = 16; o; o >>= 1)
            s += __longlong_as_double(
                 __shfl_xor_sync(0xffffffffu, __double_as_longlong(s), o));
        if (lane == 0) dred[warp] = s;
        __syncthreads();
        if (t == 0) {
            double total = 0.0;
#pragma unroll
            for (int w = 0; w < 8; w++) total += dred[w];
            double score = total / ((double)BB * PCH * NN);
            out[0] = (float)(1.0 - score / (double)NN);
            g_count = 0;                   // reset for next graph replay
        }
    }
}

extern "C" void kernel_launch(void* const* d_in, const int* in_sizes, int n_in,
                              void* d_out, int out_size) {
    const float* f = (const float*)d_in[0];
    const float* p = (const float*)d_in[1];
    precompute_kernel<<<(BB * NN + 63) / 64, 64>>>(f, p);
    pair_kernel<<<NLAUNCH, 256>>>((float*)d_out);
}